// round 4
// baseline (speedup 1.0000x reference)
#include <cuda_runtime.h>
#include <cstdint>

// ---------------------------------------------------------------------------
// GCN layer: out = relu( (A x) @ W + b )  ==  relu( A (x@W) + b )
// Plan:
//   1) CSR build (zero deg -> histogram -> scan -> scatter packed {col,val})
//   2) y = x @ W   (fp32x2 tiled GEMM)  -> scratch g_y
//   3) gather: out[b,r] = relu( b + sum_e v_e * y[b, col_e] )   (no atomics,
//      broadcast record loads, 4-deep gather pipelining)
// ---------------------------------------------------------------------------

#define C_DIM 128
static constexpr int  N_NODES = 50000;
static constexpr int  B_MAX   = 4;
static constexpr int  E_MAX   = 800000;
static constexpr long Y_ELEMS = (long)B_MAX * N_NODES * C_DIM;

__device__ float                           g_y[Y_ELEMS];      // 102.4 MB
__device__ int                             g_deg[N_NODES];
__device__ int                             g_off[N_NODES + 1];
__device__ int                             g_cur[N_NODES];
__device__ __align__(16) unsigned long long g_ebuf[E_MAX];    // {val:hi, col:lo}

// ---------------------------------------------------------------------------
// f32x2 packed helpers
// ---------------------------------------------------------------------------
__device__ __forceinline__ unsigned long long pack2(float lo, float hi) {
    unsigned long long r;
    asm("mov.b64 %0, {%1, %2};" : "=l"(r) : "f"(lo), "f"(hi));
    return r;
}
__device__ __forceinline__ void unpack2(unsigned long long p, float& lo, float& hi) {
    asm("mov.b64 {%0, %1}, %2;" : "=f"(lo), "=f"(hi) : "l"(p));
}
__device__ __forceinline__ void fma2(unsigned long long& d,
                                     unsigned long long a,
                                     unsigned long long b) {
    asm("fma.rn.f32x2 %0, %1, %2, %0;" : "+l"(d) : "l"(a), "l"(b));
}

// ---------------------------------------------------------------------------
// CSR build
// ---------------------------------------------------------------------------
__global__ void zero_deg_kernel(int n) {
    int i = blockIdx.x * blockDim.x + threadIdx.x;
    if (i < n) g_deg[i] = 0;
}

__global__ void hist_kernel(const int* __restrict__ er, int E) {
    int e = blockIdx.x * blockDim.x + threadIdx.x;
    if (e < E) atomicAdd(&g_deg[er[e]], 1);
}

__global__ void __launch_bounds__(1024) scan_kernel(int N) {
    __shared__ int part[1024];
    const int tid   = threadIdx.x;
    const int chunk = (N + 1023) / 1024;
    const int s = tid * chunk;
    const int e = min(s + chunk, N);

    int sum = 0;
    for (int i = s; i < e; ++i) sum += g_deg[i];
    part[tid] = sum;
    __syncthreads();

    for (int ofs = 1; ofs < 1024; ofs <<= 1) {
        int v = (tid >= ofs) ? part[tid - ofs] : 0;
        __syncthreads();
        part[tid] += v;
        __syncthreads();
    }
    int run = (tid == 0) ? 0 : part[tid - 1];
    for (int i = s; i < e; ++i) {
        g_off[i] = run;
        g_cur[i] = run;
        run += g_deg[i];
    }
    if (s < N && e == N) g_off[N] = run;
}

__global__ void scatter_kernel(const int*   __restrict__ er,
                               const int*   __restrict__ ec,
                               const float* __restrict__ ev,
                               int E) {
    int e = blockIdx.x * blockDim.x + threadIdx.x;
    if (e >= E) return;
    const int pos = atomicAdd(&g_cur[er[e]], 1);
    const unsigned long long rec =
        ((unsigned long long)__float_as_uint(ev[e]) << 32) | (unsigned)ec[e];
    g_ebuf[pos] = rec;
}

// ---------------------------------------------------------------------------
// GEMM: y = x @ W   (128x128 CTA tile, 256 threads, 8x8 micro-tile, fp32x2)
// w via LDS.128 (conflict-light), a via broadcast LDS.64, 2 k's per step.
// ---------------------------------------------------------------------------
__global__ void __launch_bounds__(256)
gemm_kernel(const float* __restrict__ x,
            const float* __restrict__ W,
            int total_rows) {
    extern __shared__ float sm[];
    float* As = sm;                 // [128][128]
    float* Ws = sm + 128 * 128;     // [128][128]

    const int  tid  = threadIdx.x;
    const long row0 = (long)blockIdx.x * 128;

    {
        const float4* Wg = reinterpret_cast<const float4*>(W);
        float4*       Wd = reinterpret_cast<float4*>(Ws);
        for (int i = tid; i < 4096; i += 256) Wd[i] = Wg[i];
    }
    {
        const float4* Ag = reinterpret_cast<const float4*>(x);
        float4*       Ad = reinterpret_cast<float4*>(As);
        for (int i = tid; i < 4096; i += 256) {
            const int  r  = i >> 5;
            const int  c4 = i & 31;
            const long gr = row0 + r;
            Ad[i] = (gr < total_rows) ? Ag[gr * 32 + c4]
                                      : make_float4(0.f, 0.f, 0.f, 0.f);
        }
    }
    __syncthreads();

    const int tx = tid & 15;   // cols [tx*8, tx*8+8)
    const int ty = tid >> 4;   // rows [ty*8, ty*8+8)

    unsigned long long acc[8][4];
#pragma unroll
    for (int r = 0; r < 8; ++r)
#pragma unroll
        for (int cp = 0; cp < 4; ++cp) acc[r][cp] = 0ULL;

    const float* a_base = As + ty * 8 * 128;

#pragma unroll 2
    for (int k = 0; k < 128; k += 2) {
        // w for k and k+1: 4x LDS.128
        const float4* wk0 = reinterpret_cast<const float4*>(Ws + k * 128 + tx * 8);
        const float4* wk1 = reinterpret_cast<const float4*>(Ws + (k + 1) * 128 + tx * 8);
        const float4 wa0 = wk0[0], wa1 = wk0[1];
        const float4 wb0 = wk1[0], wb1 = wk1[1];
        const unsigned long long w0a = pack2(wa0.x, wa0.y);
        const unsigned long long w1a = pack2(wa0.z, wa0.w);
        const unsigned long long w2a = pack2(wa1.x, wa1.y);
        const unsigned long long w3a = pack2(wa1.z, wa1.w);
        const unsigned long long w0b = pack2(wb0.x, wb0.y);
        const unsigned long long w1b = pack2(wb0.z, wb0.w);
        const unsigned long long w2b = pack2(wb1.x, wb1.y);
        const unsigned long long w3b = pack2(wb1.z, wb1.w);
#pragma unroll
        for (int r = 0; r < 8; ++r) {
            const float2 a2 = *reinterpret_cast<const float2*>(a_base + r * 128 + k);
            const unsigned long long aa0 = pack2(a2.x, a2.x);
            const unsigned long long aa1 = pack2(a2.y, a2.y);
            fma2(acc[r][0], aa0, w0a);
            fma2(acc[r][1], aa0, w1a);
            fma2(acc[r][2], aa0, w2a);
            fma2(acc[r][3], aa0, w3a);
            fma2(acc[r][0], aa1, w0b);
            fma2(acc[r][1], aa1, w1b);
            fma2(acc[r][2], aa1, w2b);
            fma2(acc[r][3], aa1, w3b);
        }
    }

#pragma unroll
    for (int r = 0; r < 8; ++r) {
        const long gr = row0 + ty * 8 + r;
        if (gr >= total_rows) continue;
        float o[8];
#pragma unroll
        for (int cp = 0; cp < 4; ++cp)
            unpack2(acc[r][cp], o[2 * cp], o[2 * cp + 1]);
        float4* op = reinterpret_cast<float4*>(g_y + gr * C_DIM + tx * 8);
        op[0] = make_float4(o[0], o[1], o[2], o[3]);
        op[1] = make_float4(o[4], o[5], o[6], o[7]);
    }
}

// ---------------------------------------------------------------------------
// Gather: out[b,n,:] = relu( bias + sum_e val_e * y[b, col_e, :] )
// One warp per row; lane owns 4 channels (float4). Edge records loaded by
// ALL lanes at the same address (broadcast LDG, no shfl). Edge loop unrolled
// x4 with 4 independent accumulators (MLP=4 gathers in flight).
// ---------------------------------------------------------------------------
__global__ void __launch_bounds__(256)
gather_kernel(const float* __restrict__ bias,
              float*       __restrict__ out,
              int N) {
    const int lane = threadIdx.x & 31;
    const int warp = threadIdx.x >> 5;
    const int b    = blockIdx.y;

    const float4* yb    = reinterpret_cast<const float4*>(g_y) + (size_t)b * N * 32;
    const float4  bias4 = __ldg(reinterpret_cast<const float4*>(bias) + lane);

    const int n_base = blockIdx.x * 64;

#pragma unroll 1
    for (int i = 0; i < 8; ++i) {
        const int n = n_base + warp * 8 + i;
        if (n >= N) return;

        const int st = __ldg(&g_off[n]);
        const int en = __ldg(&g_off[n + 1]);

        float4 a0 = make_float4(0.f, 0.f, 0.f, 0.f);
        float4 a1 = make_float4(0.f, 0.f, 0.f, 0.f);
        float4 a2 = make_float4(0.f, 0.f, 0.f, 0.f);
        float4 a3 = make_float4(0.f, 0.f, 0.f, 0.f);

        int e = st;
        for (; e + 4 <= en; e += 4) {
            const unsigned long long p0 = __ldg(&g_ebuf[e]);
            const unsigned long long p1 = __ldg(&g_ebuf[e + 1]);
            const unsigned long long p2 = __ldg(&g_ebuf[e + 2]);
            const unsigned long long p3 = __ldg(&g_ebuf[e + 3]);
            const int c0 = (int)(p0 & 0xffffffffu);
            const int c1 = (int)(p1 & 0xffffffffu);
            const int c2 = (int)(p2 & 0xffffffffu);
            const int c3 = (int)(p3 & 0xffffffffu);
            const float v0 = __uint_as_float((unsigned)(p0 >> 32));
            const float v1 = __uint_as_float((unsigned)(p1 >> 32));
            const float v2 = __uint_as_float((unsigned)(p2 >> 32));
            const float v3 = __uint_as_float((unsigned)(p3 >> 32));
            const float4 x0 = __ldg(yb + (size_t)c0 * 32 + lane);
            const float4 x1 = __ldg(yb + (size_t)c1 * 32 + lane);
            const float4 x2 = __ldg(yb + (size_t)c2 * 32 + lane);
            const float4 x3 = __ldg(yb + (size_t)c3 * 32 + lane);
            a0.x = fmaf(v0, x0.x, a0.x); a0.y = fmaf(v0, x0.y, a0.y);
            a0.z = fmaf(v0, x0.z, a0.z); a0.w = fmaf(v0, x0.w, a0.w);
            a1.x = fmaf(v1, x1.x, a1.x); a1.y = fmaf(v1, x1.y, a1.y);
            a1.z = fmaf(v1, x1.z, a1.z); a1.w = fmaf(v1, x1.w, a1.w);
            a2.x = fmaf(v2, x2.x, a2.x); a2.y = fmaf(v2, x2.y, a2.y);
            a2.z = fmaf(v2, x2.z, a2.z); a2.w = fmaf(v2, x2.w, a2.w);
            a3.x = fmaf(v3, x3.x, a3.x); a3.y = fmaf(v3, x3.y, a3.y);
            a3.z = fmaf(v3, x3.z, a3.z); a3.w = fmaf(v3, x3.w, a3.w);
        }
        for (; e < en; ++e) {
            const unsigned long long p0 = __ldg(&g_ebuf[e]);
            const int   c0 = (int)(p0 & 0xffffffffu);
            const float v0 = __uint_as_float((unsigned)(p0 >> 32));
            const float4 x0 = __ldg(yb + (size_t)c0 * 32 + lane);
            a0.x = fmaf(v0, x0.x, a0.x); a0.y = fmaf(v0, x0.y, a0.y);
            a0.z = fmaf(v0, x0.z, a0.z); a0.w = fmaf(v0, x0.w, a0.w);
        }

        float4 r;
        r.x = fmaxf((a0.x + a1.x) + (a2.x + a3.x) + bias4.x, 0.f);
        r.y = fmaxf((a0.y + a1.y) + (a2.y + a3.y) + bias4.y, 0.f);
        r.z = fmaxf((a0.z + a1.z) + (a2.z + a3.z) + bias4.z, 0.f);
        r.w = fmaxf((a0.w + a1.w) + (a2.w + a3.w) + bias4.w, 0.f);

        reinterpret_cast<float4*>(out)[((size_t)b * N + n) * 32 + lane] = r;
    }
}

// ---------------------------------------------------------------------------
// Launch
// ---------------------------------------------------------------------------
extern "C" void kernel_launch(void* const* d_in, const int* in_sizes, int n_in,
                              void* d_out, int out_size) {
    const float* x    = (const float*)d_in[0];
    const int*   er   = (const int*)  d_in[1];
    const int*   ec   = (const int*)  d_in[2];
    const float* ev   = (const float*)d_in[3];
    const float* W    = (const float*)d_in[4];
    const float* bias = (const float*)d_in[5];
    float*       out  = (float*)d_out;

    const int E  = in_sizes[1];
    const int C  = in_sizes[5];            // 128
    const int BN = in_sizes[0] / C;        // B*N
    const int N  = N_NODES;
    const int B  = BN / N;

    // 1) CSR build
    zero_deg_kernel<<<(N + 255) / 256, 256>>>(N);
    hist_kernel<<<(E + 255) / 256, 256>>>(er, E);
    scan_kernel<<<1, 1024>>>(N);
    scatter_kernel<<<(E + 255) / 256, 256>>>(er, ec, ev, E);

    // 2) y = x @ W
    cudaFuncSetAttribute(gemm_kernel,
                         cudaFuncAttributeMaxDynamicSharedMemorySize, 131072);
    gemm_kernel<<<(BN + 127) / 128, 256, 131072>>>(x, W, BN);

    // 3) gather + bias + relu
    dim3 ggrid((N + 63) / 64, B);
    gather_kernel<<<ggrid, 256>>>(bias, out, N);
}